// round 14
// baseline (speedup 1.0000x reference)
#include <cuda_runtime.h>
#include <cuda_fp16.h>

#define H    128   // hidden dim
#define TPB  64    // threads per block
#define PPT  8     // points per thread
#define NPR  4     // half2 point-pairs per thread (independent chains)
#define CH   8     // h-chunk size between fp32 flushes

__device__ __forceinline__ unsigned h2u(__half2 v) {
    return *reinterpret_cast<unsigned*>(&v);
}
__device__ __forceinline__ __half2 u2h(unsigned v) {
    return *reinterpret_cast<__half2*>(&v);
}

__global__ __launch_bounds__(TPB)
void cubeflow_fused_kernel(const float* __restrict__ input,
                           const float* __restrict__ latent,
                           const float* __restrict__ W1,
                           const float* __restrict__ b1,
                           const float* __restrict__ W2,
                           const float* __restrict__ b2,
                           float* __restrict__ out,
                           int P, int BP)
{
    // fp16 weights, each half2 = (w,w) duplicated.
    __shared__ uint4 sW[H];        // {w0w0, w1w1, w2w2, bTbT}  bT = w3*theta+b1
    __shared__ uint4 sV[H / 2];    // {v0(h),v1(h), v0(h+1),v1(h+1)} 2 h per entry

    const int tid = threadIdx.x;

    // theta uniform per block (block spans 512 contiguous points in one batch)
    const int   bidx  = (blockIdx.x * (TPB * PPT)) / P;
    const float theta = latent[bidx] * 10.0f;

    // stage weights: 64 threads cover 128 h in 2 steps
    #pragma unroll
    for (int h = tid; h < H; h += TPB) {
        const float4 r = reinterpret_cast<const float4*>(W1)[h];
        const float bT = fmaf(r.w, theta, b1[h]);
        sW[h] = make_uint4(h2u(__float2half2_rn(r.x)),
                           h2u(__float2half2_rn(r.y)),
                           h2u(__float2half2_rn(r.z)),
                           h2u(__float2half2_rn(bT)));
    }
    if (tid < H / 2) {
        const int h0 = 2 * tid, h1 = h0 + 1;
        sV[tid] = make_uint4(h2u(__float2half2_rn(W2[h0])),
                             h2u(__float2half2_rn(W2[H + h0])),
                             h2u(__float2half2_rn(W2[h1])),
                             h2u(__float2half2_rn(W2[H + h1])));
    }

    const int unit = blockIdx.x * TPB + tid;      // one unit = 8 points
    const int p0   = unit * PPT;

    // 8 points * 3 coords = 6 coalesced float4 loads
    const float4* in4 = reinterpret_cast<const float4*>(input) + (size_t)unit * 6;
    float4 q[6];
    #pragma unroll
    for (int i = 0; i < 6; ++i) q[i] = in4[i];
    const float* qf = reinterpret_cast<const float*>(q);

    float x0[PPT], x1[PPT], x2[PPT];
    #pragma unroll
    for (int k = 0; k < PPT; ++k) {
        x0[k] = qf[3 * k + 0];
        x1[k] = qf[3 * k + 1];
        x2[k] = qf[3 * k + 2];
    }

    // ---- exact fp32 outputs first: con + eval ----
    {
        float4* conp = reinterpret_cast<float4*>(out + BP) + p0;
        #pragma unroll
        for (int k = 0; k < PPT; ++k)
            conp[k] = make_float4(x0[k], x1[k], x2[k], theta);

        float sn, cs;
        sincosf(theta, &sn, &cs);
        float ev[PPT];
        #pragma unroll
        for (int k = 0; k < PPT; ++k) {
            const float d0 = x0[k] - theta, d1 = x1[k], d2 = x2[k];
            const float f1 = 1.4f * d0 * d0 + 1.4f * d1 * d1
                           + 0.2f * d2 * d2 - 0.5f;
            const float a2  = d2 + 0.4f;
            const float c20 = d0 * cs + d1 * sn;
            const float c21 = d1 * cs - d0 * sn;
            const float f2v = 3.8f * c20 * c20 + 0.6f * c21 * c21
                            + 3.8f * a2 * a2 - 0.5f;
            const float a3  = d2 - 0.6f;
            const float c30 = d0 * cs - d1 * sn;
            const float c31 = d0 * sn + d1 * cs;
            const float f3v = 0.35f * c30 * c30 + 2.8f * c31 * c31
                            + 2.8f * a3 * a3 - 0.5f;
            ev[k] = fminf(f1, fminf(f2v, f3v));
        }
        float4* evp = reinterpret_cast<float4*>(out + p0);
        evp[0] = make_float4(ev[0], ev[1], ev[2], ev[3]);
        evp[1] = make_float4(ev[4], ev[5], ev[6], ev[7]);
    }

    // ---- fp16 MLP: 4 independent point-pair chains, ALL 128 h ----
    __half2 X0[NPR], X1[NPR], X2[NPR];
    float2  A0[NPR], A1[NPR];
    #pragma unroll
    for (int j = 0; j < NPR; ++j) {
        X0[j] = __floats2half2_rn(x0[2 * j], x0[2 * j + 1]);
        X1[j] = __floats2half2_rn(x1[2 * j], x1[2 * j + 1]);
        X2[j] = __floats2half2_rn(x2[2 * j], x2[2 * j + 1]);
        A0[j] = make_float2(0.f, 0.f);
        A1[j] = make_float2(0.f, 0.f);
    }

    __syncthreads();   // weights staged

    const __half2 zero = __float2half2_rn(0.f);

    #pragma unroll 1
    for (int c = 0; c < H / CH; ++c) {              // 16 chunks of 8 h
        __half2 P0[NPR], P1[NPR];                   // fp16 partials (8-h window)
        #pragma unroll
        for (int j = 0; j < NPR; ++j) { P0[j] = zero; P1[j] = zero; }

        #pragma unroll
        for (int i = 0; i < CH; ++i) {
            const uint4 w = sW[c * CH + i];
            const uint4 v = sV[c * (CH / 2) + (i >> 1)];
            const __half2 w0 = u2h(w.x), w1 = u2h(w.y);
            const __half2 w2 = u2h(w.z), bT = u2h(w.w);
            const __half2 v0 = u2h((i & 1) ? v.z : v.x);   // compile-time select
            const __half2 v1 = u2h((i & 1) ? v.w : v.y);
            #pragma unroll
            for (int j = 0; j < NPR; ++j) {                // 4 independent chains
                __half2 t = __hfma2(w0, X0[j],
                            __hfma2(w1, X1[j],
                            __hfma2(w2, X2[j], bT)));
                t = __hmax2(t, zero);                      // relu
                P0[j] = __hfma2(v0, t, P0[j]);
                P1[j] = __hfma2(v1, t, P1[j]);
            }
        }

        #pragma unroll
        for (int j = 0; j < NPR; ++j) {             // flush to fp32
            const float2 f0 = __half22float2(P0[j]);
            const float2 f1 = __half22float2(P1[j]);
            A0[j].x += f0.x;  A0[j].y += f0.y;
            A1[j].x += f1.x;  A1[j].y += f1.y;
        }
    }

    const float b20 = __ldg(b2), b21 = __ldg(b2 + 1);
    float4* prp = reinterpret_cast<float4*>(out + (size_t)5 * BP
                                            + (size_t)p0 * 2);
    #pragma unroll
    for (int j = 0; j < NPR; ++j)
        prp[j] = make_float4(A0[j].x + b20, A1[j].x + b21,
                             A0[j].y + b20, A1[j].y + b21);
}

extern "C" void kernel_launch(void* const* d_in, const int* in_sizes, int n_in,
                              void* d_out, int out_size)
{
    const float* input  = (const float*)d_in[0];
    const float* latent = (const float*)d_in[1];
    const float* W1     = (const float*)d_in[2];
    const float* b1     = (const float*)d_in[3];
    const float* W2     = (const float*)d_in[4];
    const float* b2     = (const float*)d_in[5];
    float*       out    = (float*)d_out;

    const int BP = in_sizes[0] / 3;        // total points (B*P)
    const int B  = in_sizes[1];            // latent element count == batch
    const int P  = BP / B;
    const int blocks = BP / (TPB * PPT);   // 1024 -> 6.92 blocks/SM, one wave

    cubeflow_fused_kernel<<<blocks, TPB>>>(input, latent, W1, b1, W2, b2,
                                           out, P, BP);
}

// round 15
// speedup vs baseline: 1.0828x; 1.0828x over previous
#include <cuda_runtime.h>
#include <cuda_fp16.h>

#define H    128   // hidden dim
#define HPH  64    // h per half
#define TPB  128   // threads per block (two 64-thread halves)
#define UPB  64    // point-units per block
#define PPT  8     // points per unit
#define NPR  4     // half2 point-pairs per thread (independent chains)
#define CH   8     // h-chunk size between fp32 flushes

__device__ __forceinline__ unsigned h2u(__half2 v) {
    return *reinterpret_cast<unsigned*>(&v);
}
__device__ __forceinline__ __half2 u2h(unsigned v) {
    return *reinterpret_cast<__half2*>(&v);
}

__global__ __launch_bounds__(TPB)
void cubeflow_fused_kernel(const float* __restrict__ input,
                           const float* __restrict__ latent,
                           const float* __restrict__ W1,
                           const float* __restrict__ b1,
                           const float* __restrict__ W2,
                           const float* __restrict__ b2,
                           float* __restrict__ out,
                           int P, int BP)
{
    // fp16 weights, each half2 = (w,w) duplicated.
    __shared__ uint4  sW[H];       // {w0w0, w1w1, w2w2, bTbT}  bT = w3*theta+b1
    __shared__ uint4  sV[H / 2];   // {v0(h),v1(h), v0(h+1),v1(h+1)} 2 h per entry
    __shared__ float4 red[UPB][NPR];  // cross-half partial probs

    const int tid    = threadIdx.x;
    const int wg_tid = tid & (UPB - 1);
    const int half   = tid >> 6;                  // 0: h[0,64)  1: h[64,128)

    // theta uniform per block (block spans 512 contiguous points in one batch)
    const int   bidx  = (blockIdx.x * (UPB * PPT)) / P;
    const float theta = latent[bidx] * 10.0f;

    // stage weights (128 threads cover 128 h)
    {
        const float4 r = reinterpret_cast<const float4*>(W1)[tid];
        const float bT = fmaf(r.w, theta, b1[tid]);
        sW[tid] = make_uint4(h2u(__float2half2_rn(r.x)),
                             h2u(__float2half2_rn(r.y)),
                             h2u(__float2half2_rn(r.z)),
                             h2u(__float2half2_rn(bT)));
    }
    if (tid < H / 2) {
        const int h0 = 2 * tid, h1 = h0 + 1;
        sV[tid] = make_uint4(h2u(__float2half2_rn(W2[h0])),
                             h2u(__float2half2_rn(W2[H + h0])),
                             h2u(__float2half2_rn(W2[h1])),
                             h2u(__float2half2_rn(W2[H + h1])));
    }

    const int unit = blockIdx.x * UPB + wg_tid;   // one unit = 8 points
    const int p0   = unit * PPT;

    // 8 points * 3 coords = 6 coalesced float4 loads (both halves load)
    const float4* in4 = reinterpret_cast<const float4*>(input) + (size_t)unit * 6;
    float4 q[6];
    #pragma unroll
    for (int i = 0; i < 6; ++i) q[i] = in4[i];
    const float* qf = reinterpret_cast<const float*>(q);

    float x0[PPT], x1[PPT], x2[PPT];
    #pragma unroll
    for (int k = 0; k < PPT; ++k) {
        x0[k] = qf[3 * k + 0];
        x1[k] = qf[3 * k + 1];
        x2[k] = qf[3 * k + 2];
    }

    // ---- exact fp32 outputs, split across halves (overlap) ----
    if (half == 0) {
        float4* conp = reinterpret_cast<float4*>(out + BP) + p0;
        #pragma unroll
        for (int k = 0; k < PPT; ++k)
            conp[k] = make_float4(x0[k], x1[k], x2[k], theta);
    } else {
        float sn, cs;
        sincosf(theta, &sn, &cs);
        float ev[PPT];
        #pragma unroll
        for (int k = 0; k < PPT; ++k) {
            const float d0 = x0[k] - theta, d1 = x1[k], d2 = x2[k];
            const float f1 = 1.4f * d0 * d0 + 1.4f * d1 * d1
                           + 0.2f * d2 * d2 - 0.5f;
            const float a2  = d2 + 0.4f;
            const float c20 = d0 * cs + d1 * sn;
            const float c21 = d1 * cs - d0 * sn;
            const float f2v = 3.8f * c20 * c20 + 0.6f * c21 * c21
                            + 3.8f * a2 * a2 - 0.5f;
            const float a3  = d2 - 0.6f;
            const float c30 = d0 * cs - d1 * sn;
            const float c31 = d0 * sn + d1 * cs;
            const float f3v = 0.35f * c30 * c30 + 2.8f * c31 * c31
                            + 2.8f * a3 * a3 - 0.5f;
            ev[k] = fminf(f1, fminf(f2v, f3v));
        }
        float4* evp = reinterpret_cast<float4*>(out + p0);
        evp[0] = make_float4(ev[0], ev[1], ev[2], ev[3]);
        evp[1] = make_float4(ev[4], ev[5], ev[6], ev[7]);
    }

    // ---- fp16 MLP: 4 independent point-pair chains over this half's 64 h ----
    __half2 X0[NPR], X1[NPR], X2[NPR];
    float2  A0[NPR], A1[NPR];
    #pragma unroll
    for (int j = 0; j < NPR; ++j) {
        X0[j] = __floats2half2_rn(x0[2 * j], x0[2 * j + 1]);
        X1[j] = __floats2half2_rn(x1[2 * j], x1[2 * j + 1]);
        X2[j] = __floats2half2_rn(x2[2 * j], x2[2 * j + 1]);
        A0[j] = make_float2(0.f, 0.f);
        A1[j] = make_float2(0.f, 0.f);
    }

    __syncthreads();   // weights staged

    const uint4* pw = sW + half * HPH;
    const uint4* pv = sV + half * (HPH / 2);
    const __half2 zero = __float2half2_rn(0.f);

    #pragma unroll 1
    for (int c = 0; c < HPH / CH; ++c) {            // 8 chunks of 8 h
        __half2 P0[NPR], P1[NPR];                   // fp16 partials (8-h window)
        #pragma unroll
        for (int j = 0; j < NPR; ++j) { P0[j] = zero; P1[j] = zero; }

        #pragma unroll
        for (int i = 0; i < CH; ++i) {
            const uint4 w = pw[c * CH + i];
            const uint4 v = pv[c * (CH / 2) + (i >> 1)];
            const __half2 w0 = u2h(w.x), w1 = u2h(w.y);
            const __half2 w2 = u2h(w.z), bT = u2h(w.w);
            const __half2 v0 = u2h((i & 1) ? v.z : v.x);   // compile-time select
            const __half2 v1 = u2h((i & 1) ? v.w : v.y);
            #pragma unroll
            for (int j = 0; j < NPR; ++j) {                // 4 independent chains
                __half2 t = __hfma2(w0, X0[j],
                            __hfma2(w1, X1[j],
                            __hfma2(w2, X2[j], bT)));
                t = __hmax2(t, zero);                      // relu
                P0[j] = __hfma2(v0, t, P0[j]);
                P1[j] = __hfma2(v1, t, P1[j]);
            }
        }

        #pragma unroll
        for (int j = 0; j < NPR; ++j) {             // flush to fp32
            const float2 f0 = __half22float2(P0[j]);
            const float2 f1 = __half22float2(P1[j]);
            A0[j].x += f0.x;  A0[j].y += f0.y;
            A1[j].x += f1.x;  A1[j].y += f1.y;
        }
    }

    // ---- cross-half reduction + store ----
    if (half == 1) {
        #pragma unroll
        for (int j = 0; j < NPR; ++j)
            red[wg_tid][j] = make_float4(A0[j].x, A1[j].x, A0[j].y, A1[j].y);
    }
    __syncthreads();

    if (half == 0) {
        const float b20 = __ldg(b2), b21 = __ldg(b2 + 1);
        float4* prp = reinterpret_cast<float4*>(out + (size_t)5 * BP
                                                + (size_t)p0 * 2);
        #pragma unroll
        for (int j = 0; j < NPR; ++j) {
            const float4 r = red[wg_tid][j];
            prp[j] = make_float4(A0[j].x + r.x + b20, A1[j].x + r.y + b21,
                                 A0[j].y + r.z + b20, A1[j].y + r.w + b21);
        }
    }
}

extern "C" void kernel_launch(void* const* d_in, const int* in_sizes, int n_in,
                              void* d_out, int out_size)
{
    const float* input  = (const float*)d_in[0];
    const float* latent = (const float*)d_in[1];
    const float* W1     = (const float*)d_in[2];
    const float* b1     = (const float*)d_in[3];
    const float* W2     = (const float*)d_in[4];
    const float* b2     = (const float*)d_in[5];
    float*       out    = (float*)d_out;

    const int BP = in_sizes[0] / 3;        // total points (B*P)
    const int B  = in_sizes[1];            // latent element count == batch
    const int P  = BP / B;
    const int blocks = BP / (UPB * PPT);   // 1024 -> single wave

    cubeflow_fused_kernel<<<blocks, TPB>>>(input, latent, W1, b1, W2, b2,
                                           out, P, BP);
}

// round 16
// speedup vs baseline: 1.0845x; 1.0015x over previous
#include <cuda_runtime.h>
#include <cuda_fp16.h>

typedef unsigned long long ull;

// ---- f32x2 packed helpers ----
__device__ __forceinline__ ull pk(float lo, float hi) {
    ull r;
    asm("mov.b64 %0, {%1,%2};" : "=l"(r)
        : "r"(__float_as_uint(lo)), "r"(__float_as_uint(hi)));
    return r;
}
__device__ __forceinline__ void upk(ull v, float& lo, float& hi) {
    unsigned a, b;
    asm("mov.b64 {%0,%1}, %2;" : "=r"(a), "=r"(b) : "l"(v));
    lo = __uint_as_float(a);
    hi = __uint_as_float(b);
}
__device__ __forceinline__ ull fma2(ull a, ull b, ull c) {
    ull d;
    asm("fma.rn.f32x2 %0, %1, %2, %3;" : "=l"(d) : "l"(a), "l"(b), "l"(c));
    return d;
}
// ---- fp16 helpers ----
__device__ __forceinline__ unsigned h2u(__half2 v) { return *reinterpret_cast<unsigned*>(&v); }
__device__ __forceinline__ __half2 u2h(unsigned v) { return *reinterpret_cast<__half2*>(&v); }

#define H    128
#define TPB  256   // warps 0-3: fp32 half (h[0,64)), warps 4-7: fp16 half (h[64,128))
#define UPB  128   // point-units per block
#define PPT  4     // points per unit

__global__ __launch_bounds__(TPB)
void cubeflow_dualpipe_kernel(const float* __restrict__ input,
                              const float* __restrict__ latent,
                              const float* __restrict__ W1,
                              const float* __restrict__ b1,
                              const float* __restrict__ W2,
                              const float* __restrict__ b2,
                              float* __restrict__ out,
                              int P, int BP)
{
    // fp32 half: even/odd-h packed fp32 weights (h-pairs 0..31 -> h[0,64))
    __shared__ float4 sA[32];    // (w0e,w0o, w1e,w1o)
    __shared__ float4 sB[32];    // (w2e,w2o, bTe,bTo)
    __shared__ float4 sC[32];    // (w20e,w20o, w21e,w21o)
    // fp16 half: (w,w)-duplicated half2 weights (h[64,128))
    __shared__ uint4  sW[64];    // {w0w0, w1w1, w2w2, bTbT}
    __shared__ uint4  sV[32];    // {v0,v1, v0',v1'} for 2 h
    __shared__ float4 redA[UPB]; // cross-half partial probs (pts 0,1)
    __shared__ float4 redB[UPB]; // cross-half partial probs (pts 2,3)

    const int tid    = threadIdx.x;
    const int wg_tid = tid & (UPB - 1);
    const int half   = tid >> 7;                 // 0: fp32 h[0,64)  1: fp16 h[64,128)

    // theta uniform per block (block spans 512 contiguous points in one batch)
    const int   bidx  = (blockIdx.x * (UPB * PPT)) / P;
    const float theta = latent[bidx] * 10.0f;

    // ---- stage weights ----
    if (tid < 32) {                              // fp32-half weights, h-pairs 0..31
        const int h0 = 2 * tid, h1 = h0 + 1;
        const float4 r0 = reinterpret_cast<const float4*>(W1)[h0];
        const float4 r1 = reinterpret_cast<const float4*>(W1)[h1];
        sA[tid] = make_float4(r0.x, r1.x, r0.y, r1.y);
        sB[tid] = make_float4(r0.z, r1.z,
                              fmaf(r0.w, theta, b1[h0]),
                              fmaf(r1.w, theta, b1[h1]));
        sC[tid] = make_float4(W2[h0], W2[h1], W2[H + h0], W2[H + h1]);
    } else if (tid >= 64 && tid < 128) {         // fp16-half weights, h = tid (64..127)
        const int h = tid;
        const float4 r = reinterpret_cast<const float4*>(W1)[h];
        const float bT = fmaf(r.w, theta, b1[h]);
        sW[h - 64] = make_uint4(h2u(__float2half2_rn(r.x)),
                                h2u(__float2half2_rn(r.y)),
                                h2u(__float2half2_rn(r.z)),
                                h2u(__float2half2_rn(bT)));
    } else if (tid >= 128 && tid < 160) {        // fp16-half W2, pairs in h[64,128)
        const int i = tid - 128;
        const int h0 = 64 + 2 * i, h1 = h0 + 1;
        sV[i] = make_uint4(h2u(__float2half2_rn(W2[h0])),
                           h2u(__float2half2_rn(W2[H + h0])),
                           h2u(__float2half2_rn(W2[h1])),
                           h2u(__float2half2_rn(W2[H + h1])));
    }

    const int unit = blockIdx.x * UPB + wg_tid;  // one unit = 4 points
    const int p0   = unit * PPT;

    // 4 points * 3 coords = 3 coalesced float4 loads (both halves load)
    const float4* in4 = reinterpret_cast<const float4*>(input) + (size_t)unit * 3;
    const float4 q0 = in4[0], q1 = in4[1], q2 = in4[2];
    const float x0[PPT] = { q0.x, q0.w, q1.z, q2.y };
    const float x1[PPT] = { q0.y, q1.x, q1.w, q2.z };
    const float x2[PPT] = { q0.z, q1.y, q2.x, q2.w };

    // ---- exact fp32 outputs, split across halves ----
    if (half == 0) {
        float4* conp = reinterpret_cast<float4*>(out + BP) + p0;
        #pragma unroll
        for (int k = 0; k < PPT; ++k)
            conp[k] = make_float4(x0[k], x1[k], x2[k], theta);
    } else {
        float sn, cs;
        sincosf(theta, &sn, &cs);
        float ev[PPT];
        #pragma unroll
        for (int k = 0; k < PPT; ++k) {
            const float d0 = x0[k] - theta, d1 = x1[k], d2 = x2[k];
            const float f1 = 1.4f * d0 * d0 + 1.4f * d1 * d1
                           + 0.2f * d2 * d2 - 0.5f;
            const float a2  = d2 + 0.4f;
            const float c20 = d0 * cs + d1 * sn;
            const float c21 = d1 * cs - d0 * sn;
            const float f2v = 3.8f * c20 * c20 + 0.6f * c21 * c21
                            + 3.8f * a2 * a2 - 0.5f;
            const float a3  = d2 - 0.6f;
            const float c30 = d0 * cs - d1 * sn;
            const float c31 = d0 * sn + d1 * cs;
            const float f3v = 0.35f * c30 * c30 + 2.8f * c31 * c31
                            + 2.8f * a3 * a3 - 0.5f;
            ev[k] = fminf(f1, fminf(f2v, f3v));
        }
        *reinterpret_cast<float4*>(out + p0) =
            make_float4(ev[0], ev[1], ev[2], ev[3]);
    }

    __syncthreads();   // weights staged

    float pr0[PPT], pr1[PPT];   // this half's partial probs per point

    if (half == 0) {
        // ================= fp32 f32x2 path: h[0,64), even/odd lanes ========
        ull X0[PPT], X1[PPT], X2[PPT], A0[PPT], A1[PPT];
        #pragma unroll
        for (int k = 0; k < PPT; ++k) {
            X0[k] = pk(x0[k], x0[k]);
            X1[k] = pk(x1[k], x1[k]);
            X2[k] = pk(x2[k], x2[k]);
            A0[k] = 0ull;
            A1[k] = 0ull;
        }
        const ulonglong2* pa = reinterpret_cast<const ulonglong2*>(sA);
        const ulonglong2* pb = reinterpret_cast<const ulonglong2*>(sB);
        const ulonglong2* pc = reinterpret_cast<const ulonglong2*>(sC);

        #pragma unroll 4
        for (int hp = 0; hp < 32; ++hp) {
            const ulonglong2 va = pa[hp];   // (w0 pair, w1 pair)
            const ulonglong2 vb = pb[hp];   // (w2 pair, biasT pair)
            const ulonglong2 vc = pc[hp];   // (w20 pair, w21 pair)
            #pragma unroll
            for (int k = 0; k < PPT; ++k) {
                ull t = fma2(va.x, X0[k],
                        fma2(va.y, X1[k],
                        fma2(vb.x, X2[k], vb.y)));
                float lo, hi;
                upk(t, lo, hi);
                lo = fmaxf(lo, 0.0f);
                hi = fmaxf(hi, 0.0f);
                t = pk(lo, hi);
                A0[k] = fma2(vc.x, t, A0[k]);
                A1[k] = fma2(vc.y, t, A1[k]);
            }
        }
        #pragma unroll
        for (int k = 0; k < PPT; ++k) {      // even+odd fold
            float l, h;
            upk(A0[k], l, h); pr0[k] = l + h;
            upk(A1[k], l, h); pr1[k] = l + h;
        }
    } else {
        // ================= fp16 HFMA2 path: h[64,128), 2 pts per lane ======
        __half2 X0[2], X1[2], X2[2];
        float2  A0[2], A1[2];
        #pragma unroll
        for (int j = 0; j < 2; ++j) {
            X0[j] = __floats2half2_rn(x0[2 * j], x0[2 * j + 1]);
            X1[j] = __floats2half2_rn(x1[2 * j], x1[2 * j + 1]);
            X2[j] = __floats2half2_rn(x2[2 * j], x2[2 * j + 1]);
            A0[j] = make_float2(0.f, 0.f);
            A1[j] = make_float2(0.f, 0.f);
        }
        const __half2 zero = __float2half2_rn(0.f);

        #pragma unroll 1
        for (int c = 0; c < 8; ++c) {            // 8 chunks of 8 h
            __half2 P0[2], P1[2];
            #pragma unroll
            for (int j = 0; j < 2; ++j) { P0[j] = zero; P1[j] = zero; }
            #pragma unroll
            for (int i = 0; i < 8; ++i) {
                const uint4 w = sW[c * 8 + i];
                const uint4 v = sV[c * 4 + (i >> 1)];
                const __half2 w0 = u2h(w.x), w1 = u2h(w.y);
                const __half2 w2 = u2h(w.z), bT = u2h(w.w);
                const __half2 v0 = u2h((i & 1) ? v.z : v.x);
                const __half2 v1 = u2h((i & 1) ? v.w : v.y);
                #pragma unroll
                for (int j = 0; j < 2; ++j) {
                    __half2 t = __hfma2(w0, X0[j],
                                __hfma2(w1, X1[j],
                                __hfma2(w2, X2[j], bT)));
                    t = __hmax2(t, zero);
                    P0[j] = __hfma2(v0, t, P0[j]);
                    P1[j] = __hfma2(v1, t, P1[j]);
                }
            }
            #pragma unroll
            for (int j = 0; j < 2; ++j) {
                const float2 f0 = __half22float2(P0[j]);
                const float2 f1 = __half22float2(P1[j]);
                A0[j].x += f0.x;  A0[j].y += f0.y;
                A1[j].x += f1.x;  A1[j].y += f1.y;
            }
        }
        pr0[0] = A0[0].x;  pr0[1] = A0[0].y;  pr0[2] = A0[1].x;  pr0[3] = A0[1].y;
        pr1[0] = A1[0].x;  pr1[1] = A1[0].y;  pr1[2] = A1[1].x;  pr1[3] = A1[1].y;
    }

    // ---- cross-half reduction + store ----
    if (half == 1) {
        redA[wg_tid] = make_float4(pr0[0], pr1[0], pr0[1], pr1[1]);
        redB[wg_tid] = make_float4(pr0[2], pr1[2], pr0[3], pr1[3]);
    }
    __syncthreads();

    if (half == 0) {
        const float b20 = __ldg(b2), b21 = __ldg(b2 + 1);
        const float4 rA = redA[wg_tid];
        const float4 rB = redB[wg_tid];
        float4* prp = reinterpret_cast<float4*>(out + (size_t)5 * BP
                                                + (size_t)p0 * 2);
        prp[0] = make_float4(pr0[0] + rA.x + b20, pr1[0] + rA.y + b21,
                             pr0[1] + rA.z + b20, pr1[1] + rA.w + b21);
        prp[1] = make_float4(pr0[2] + rB.x + b20, pr1[2] + rB.y + b21,
                             pr0[3] + rB.z + b20, pr1[3] + rB.w + b21);
    }
}

extern "C" void kernel_launch(void* const* d_in, const int* in_sizes, int n_in,
                              void* d_out, int out_size)
{
    const float* input  = (const float*)d_in[0];
    const float* latent = (const float*)d_in[1];
    const float* W1     = (const float*)d_in[2];
    const float* b1     = (const float*)d_in[3];
    const float* W2     = (const float*)d_in[4];
    const float* b2     = (const float*)d_in[5];
    float*       out    = (float*)d_out;

    const int BP = in_sizes[0] / 3;        // total points (B*P)
    const int B  = in_sizes[1];            // latent element count == batch
    const int P  = BP / B;
    const int blocks = BP / (UPB * PPT);   // 1024

    cubeflow_dualpipe_kernel<<<blocks, TPB>>>(input, latent, W1, b1, W2, b2,
                                              out, P, BP);
}

// round 17
// speedup vs baseline: 1.0960x; 1.0107x over previous
#include <cuda_runtime.h>
#include <cuda_fp16.h>
#include <cstdint>

#define TPB   256
#define PPB   512            // points per block (both personalities)
#define H     128

__device__ __forceinline__ unsigned h2u(__half2 v) { return *reinterpret_cast<unsigned*>(&v); }
__device__ __forceinline__ __half2 u2h(unsigned v) { return *reinterpret_cast<__half2*>(&v); }

__device__ __forceinline__ void mma8(unsigned& d0, unsigned& d1,
                                     unsigned a0, unsigned a1, unsigned b) {
    const unsigned z = 0;
    asm volatile("mma.sync.aligned.m16n8k8.row.col.f16.f16.f16.f16 "
                 "{%0,%1},{%2,%3},{%4},{%5,%6};"
                 : "=r"(d0), "=r"(d1)
                 : "r"(a0), "r"(a1), "r"(b), "r"(z), "r"(z));
}
__device__ __forceinline__ void mma16(float* c, unsigned a0, unsigned a1,
                                      unsigned a2, unsigned a3,
                                      unsigned b0, unsigned b1) {
    asm volatile("mma.sync.aligned.m16n8k16.row.col.f32.f16.f16.f32 "
                 "{%0,%1,%2,%3},{%4,%5,%6,%7},{%8,%9},{%0,%1,%2,%3};"
                 : "+f"(c[0]), "+f"(c[1]), "+f"(c[2]), "+f"(c[3])
                 : "r"(a0), "r"(a1), "r"(a2), "r"(a3), "r"(b0), "r"(b1));
}

__device__ __forceinline__ float eval_point(float x0, float x1, float x2,
                                            float theta, float sn, float cs) {
    const float d0 = x0 - theta, d1 = x1, d2 = x2;
    const float f1 = 1.4f * d0 * d0 + 1.4f * d1 * d1 + 0.2f * d2 * d2 - 0.5f;
    const float a2 = d2 + 0.4f;
    const float c20 = d0 * cs + d1 * sn, c21 = d1 * cs - d0 * sn;
    const float f2v = 3.8f * c20 * c20 + 0.6f * c21 * c21 + 3.8f * a2 * a2 - 0.5f;
    const float a3 = d2 - 0.6f;
    const float c30 = d0 * cs - d1 * sn, c31 = d0 * sn + d1 * cs;
    const float f3v = 0.35f * c30 * c30 + 2.8f * c31 * c31 + 2.8f * a3 * a3 - 0.5f;
    return fminf(f1, fminf(f2v, f3v));
}

__global__ __launch_bounds__(TPB, 4)
void cubeflow_hybrid_kernel(const float* __restrict__ input,
                            const float* __restrict__ latent,
                            const float* __restrict__ W1,
                            const float* __restrict__ b1,
                            const float* __restrict__ W2,
                            const float* __restrict__ b2,
                            float* __restrict__ out,
                            int P, int BP)
{
    __shared__ uint4  sCon[8 * 32];     // tensor: per-warp 32-pt staging
    __shared__ uint4  sW[H];            // cuda: {w0w0,w1w1,w2w2,bTbT}
    __shared__ uint4  sV[H / 2];        // cuda: {v0,v1} for 2 h
    __shared__ float4 redA[128];
    __shared__ float4 redB[128];

    const int bid = blockIdx.x;
    const int g   = bid >> 3;
    const int r   = bid & 7;
    const int tid = threadIdx.x;

    // rate-matched split: 3/8 of blocks -> tensor pipe, 5/8 -> fma pipe
    const bool is_tensor = (r < 3);
    const int  TBASE     = (BP >> 3) * 3;            // 3/8 * BP (BP % 8 == 0)

    if (is_tensor) {
        // ============ TENSOR personality: points [0, 3BP/8) ===============
        const int t_rid = g * 3 + r;                 // 0..(3BP/8/512 - 1)
        const int lane = tid & 31;
        const int warp = tid >> 5;
        const int grp  = lane >> 2;
        const int tg   = lane & 3;
        const int wbase = t_rid * PPB + warp * 64;   // 64 pts per warp

        const float theta = latent[wbase / P] * 10.0f;
        float sn, cs;
        sincosf(theta, &sn, &cs);

        unsigned b1f[16];
        #pragma unroll
        for (int t = 0; t < 16; ++t) {
            const int h = 8 * t + grp;
            const float4 w = reinterpret_cast<const float4*>(W1)[h];
            const float bT = fmaf(w.w, theta, b1[h]);
            float lo, hi;
            if      (tg == 0) { lo = w.x; hi = w.y; }
            else if (tg == 1) { lo = w.z; hi = 0.f; }
            else if (tg == 2) { lo = bT;  hi = 0.f; }
            else              { lo = 0.f; hi = 0.f; }
            b1f[t] = h2u(__floats2half2_rn(lo, hi));
        }
        unsigned b2f0[8], b2f1[8];
        #pragma unroll
        for (int u = 0; u < 8; ++u) {
            if (grp < 2) {
                const float* wr = W2 + grp * 128 + 16 * u + 2 * tg;
                b2f0[u] = h2u(__floats2half2_rn(wr[0], wr[1]));
                b2f1[u] = h2u(__floats2half2_rn(wr[8], wr[9]));
            } else { b2f0[u] = 0u; b2f1[u] = 0u; }
        }

        const float b20 = __ldg(b2), b21 = __ldg(b2 + 1);
        const __half2 hz = __float2half2_rn(0.0f);
        const uint32_t* swp = reinterpret_cast<const uint32_t*>(sCon);
        const int abase = (warp * 32 + grp) * 4 + tg;

        #pragma unroll 1
        for (int t = 0; t < 2; ++t) {
            const int tp0 = wbase + t * 32;
            const int p   = tp0 + lane;

            const float* ip = input + (size_t)p * 3;
            const float x0 = ip[0], x1 = ip[1], x2 = ip[2];
            sCon[warp * 32 + lane] =
                make_uint4(h2u(__floats2half2_rn(x0, x1)),
                           h2u(__floats2half2_rn(x2, 0.0f)),
                           h2u(__floats2half2_rn(1.0f, 0.0f)), 0u);

            reinterpret_cast<float4*>(out + BP)[p] = make_float4(x0, x1, x2, theta);
            out[p] = eval_point(x0, x1, x2, theta, sn, cs);

            __syncwarp();
            const unsigned a00 = swp[abase];
            const unsigned a01 = swp[abase + 32];
            const unsigned a10 = swp[abase + 64];
            const unsigned a11 = swp[abase + 96];
            __syncwarp();

            float acc0[4] = {0.f, 0.f, 0.f, 0.f};
            float acc1[4] = {0.f, 0.f, 0.f, 0.f};

            #pragma unroll
            for (int u = 0; u < 8; ++u) {
                unsigned d0, d1, e0, e1, f0, f1, g0, g1;
                mma8(d0, d1, a00, a01, b1f[2 * u]);
                mma8(e0, e1, a00, a01, b1f[2 * u + 1]);
                mma8(f0, f1, a10, a11, b1f[2 * u]);
                mma8(g0, g1, a10, a11, b1f[2 * u + 1]);
                d0 = h2u(__hmax2(u2h(d0), hz));  d1 = h2u(__hmax2(u2h(d1), hz));
                e0 = h2u(__hmax2(u2h(e0), hz));  e1 = h2u(__hmax2(u2h(e1), hz));
                f0 = h2u(__hmax2(u2h(f0), hz));  f1 = h2u(__hmax2(u2h(f1), hz));
                g0 = h2u(__hmax2(u2h(g0), hz));  g1 = h2u(__hmax2(u2h(g1), hz));
                mma16(acc0, d0, d1, e0, e1, b2f0[u], b2f1[u]);
                mma16(acc1, f0, f1, g0, g1, b2f0[u], b2f1[u]);
            }

            if (tg == 0) {
                float2* prp = reinterpret_cast<float2*>(out + (size_t)5 * BP);
                const int q0 = tp0 + grp;
                prp[q0]      = make_float2(acc0[0] + b20, acc0[1] + b21);
                prp[q0 + 8]  = make_float2(acc0[2] + b20, acc0[3] + b21);
                prp[q0 + 16] = make_float2(acc1[0] + b20, acc1[1] + b21);
                prp[q0 + 24] = make_float2(acc1[2] + b20, acc1[3] + b21);
            }
        }
    } else {
        // ============ CUDA-core personality: points [3BP/8, BP) ===========
        const int f_rid  = g * 5 + (r - 3);          // 0..(5BP/8/512 - 1)
        const int wg_tid = tid & 127;
        const int halfid = tid >> 7;
        const int base   = TBASE + f_rid * PPB;
        const float theta = latent[base / P] * 10.0f;

        if (tid < H) {
            const float4 rr = reinterpret_cast<const float4*>(W1)[tid];
            const float bT = fmaf(rr.w, theta, b1[tid]);
            sW[tid] = make_uint4(h2u(__float2half2_rn(rr.x)),
                                 h2u(__float2half2_rn(rr.y)),
                                 h2u(__float2half2_rn(rr.z)),
                                 h2u(__float2half2_rn(bT)));
        } else if (tid < H + H / 2) {
            const int i = tid - H, h0 = 2 * i, h1 = h0 + 1;
            sV[i] = make_uint4(h2u(__float2half2_rn(W2[h0])),
                               h2u(__float2half2_rn(W2[H + h0])),
                               h2u(__float2half2_rn(W2[h1])),
                               h2u(__float2half2_rn(W2[H + h1])));
        }

        const int p0 = base + wg_tid * 4;
        const float4* in4 = reinterpret_cast<const float4*>(input + (size_t)p0 * 3);
        const float4 q0 = in4[0], q1 = in4[1], q2 = in4[2];
        const float x0[4] = { q0.x, q0.w, q1.z, q2.y };
        const float x1[4] = { q0.y, q1.x, q1.w, q2.z };
        const float x2[4] = { q0.z, q1.y, q2.x, q2.w };

        if (halfid == 0) {
            float4* conp = reinterpret_cast<float4*>(out + BP) + p0;
            #pragma unroll
            for (int k = 0; k < 4; ++k)
                conp[k] = make_float4(x0[k], x1[k], x2[k], theta);
        } else {
            float sn, cs;
            sincosf(theta, &sn, &cs);
            float ev[4];
            #pragma unroll
            for (int k = 0; k < 4; ++k)
                ev[k] = eval_point(x0[k], x1[k], x2[k], theta, sn, cs);
            *reinterpret_cast<float4*>(out + p0) =
                make_float4(ev[0], ev[1], ev[2], ev[3]);
        }

        __half2 X0[2], X1[2], X2[2];
        float2  A0[2], A1[2];
        #pragma unroll
        for (int j = 0; j < 2; ++j) {
            X0[j] = __floats2half2_rn(x0[2 * j], x0[2 * j + 1]);
            X1[j] = __floats2half2_rn(x1[2 * j], x1[2 * j + 1]);
            X2[j] = __floats2half2_rn(x2[2 * j], x2[2 * j + 1]);
            A0[j] = make_float2(0.f, 0.f);
            A1[j] = make_float2(0.f, 0.f);
        }
        __syncthreads();

        const uint4* pw = sW + halfid * 64;
        const uint4* pv = sV + halfid * 32;
        const __half2 zero = __float2half2_rn(0.f);

        #pragma unroll 1
        for (int c = 0; c < 8; ++c) {
            __half2 P0[2], P1[2];
            #pragma unroll
            for (int j = 0; j < 2; ++j) { P0[j] = zero; P1[j] = zero; }
            #pragma unroll
            for (int i = 0; i < 8; ++i) {
                const uint4 w = pw[c * 8 + i];
                const uint4 v = pv[c * 4 + (i >> 1)];
                const __half2 w0 = u2h(w.x), w1 = u2h(w.y);
                const __half2 w2 = u2h(w.z), bT = u2h(w.w);
                const __half2 v0 = u2h((i & 1) ? v.z : v.x);
                const __half2 v1 = u2h((i & 1) ? v.w : v.y);
                #pragma unroll
                for (int j = 0; j < 2; ++j) {
                    __half2 tt = __hfma2(w0, X0[j],
                                 __hfma2(w1, X1[j],
                                 __hfma2(w2, X2[j], bT)));
                    tt = __hmax2(tt, zero);
                    P0[j] = __hfma2(v0, tt, P0[j]);
                    P1[j] = __hfma2(v1, tt, P1[j]);
                }
            }
            #pragma unroll
            for (int j = 0; j < 2; ++j) {
                const float2 f0 = __half22float2(P0[j]);
                const float2 f1 = __half22float2(P1[j]);
                A0[j].x += f0.x;  A0[j].y += f0.y;
                A1[j].x += f1.x;  A1[j].y += f1.y;
            }
        }

        float pr0[4] = { A0[0].x, A0[0].y, A0[1].x, A0[1].y };
        float pr1[4] = { A1[0].x, A1[0].y, A1[1].x, A1[1].y };

        if (halfid == 1) {
            redA[wg_tid] = make_float4(pr0[0], pr1[0], pr0[1], pr1[1]);
            redB[wg_tid] = make_float4(pr0[2], pr1[2], pr0[3], pr1[3]);
        }
        __syncthreads();

        if (halfid == 0) {
            const float b20 = __ldg(b2), b21 = __ldg(b2 + 1);
            const float4 rA = redA[wg_tid];
            const float4 rB = redB[wg_tid];
            float4* prp = reinterpret_cast<float4*>(out + (size_t)5 * BP
                                                    + (size_t)p0 * 2);
            prp[0] = make_float4(pr0[0] + rA.x + b20, pr1[0] + rA.y + b21,
                                 pr0[1] + rA.z + b20, pr1[1] + rA.w + b21);
            prp[1] = make_float4(pr0[2] + rB.x + b20, pr1[2] + rB.y + b21,
                                 pr0[3] + rB.z + b20, pr1[3] + rB.w + b21);
        }
    }
}

extern "C" void kernel_launch(void* const* d_in, const int* in_sizes, int n_in,
                              void* d_out, int out_size)
{
    const float* input  = (const float*)d_in[0];
    const float* latent = (const float*)d_in[1];
    const float* W1     = (const float*)d_in[2];
    const float* b1     = (const float*)d_in[3];
    const float* W2     = (const float*)d_in[4];
    const float* b2     = (const float*)d_in[5];
    float*       out    = (float*)d_out;

    const int BP = in_sizes[0] / 3;     // total points (B*P)
    const int B  = in_sizes[1];
    const int P  = BP / B;
    const int blocks = BP / PPB;        // 1024 = 384 tensor + 640 fma, interleaved

    cubeflow_hybrid_kernel<<<blocks, TPB>>>(input, latent, W1, b1, W2, b2,
                                            out, P, BP);
}